// round 12
// baseline (speedup 1.0000x reference)
#include <cuda_runtime.h>
#include <cstdint>

#define B_  2
#define L_  4096
#define H_  8
#define D_  64
#define U_  45
#define BH_ (B_*H_)
#define CH_  128          // keys per flash chunk
#define NCH_ (L_/CH_)     // 32

// ---------------- device scratch (no allocations allowed) ----------------
__device__ int   g_idx[L_*U_];                 // sample indices
__device__ float g_M[BH_*L_];                  // sparsity measure
__device__ float g_qsel[BH_*U_*D_];            // selected Q rows, rank order
__device__ float g_pm[NCH_*BH_*U_];            // chunk max
__device__ float g_pl[NCH_*BH_*U_];            // chunk sumexp
__device__ float g_pacc[(size_t)NCH_*BH_*U_*D_]; // chunk P@V partials (5.9MB)

// ---------------- threefry2x32 (verified vs Random123 vector) ------------
__device__ __forceinline__ uint32_t rotl32(uint32_t x, int d) {
    return (x << d) | (x >> (32 - d));
}

__device__ __forceinline__ void threefry2x32(uint32_t k0, uint32_t k1,
                                             uint32_t x0, uint32_t x1,
                                             uint32_t& y0, uint32_t& y1) {
    uint32_t k2 = k0 ^ k1 ^ 0x1BD11BDAu;
    x0 += k0; x1 += k1;
#define RND(r) { x0 += x1; x1 = rotl32(x1, r); x1 ^= x0; }
    RND(13) RND(15) RND(26) RND(6)  x0 += k1; x1 += k2 + 1u;
    RND(17) RND(29) RND(16) RND(24) x0 += k2; x1 += k0 + 2u;
    RND(13) RND(15) RND(26) RND(6)  x0 += k0; x1 += k1 + 3u;
    RND(17) RND(29) RND(16) RND(24) x0 += k1; x1 += k2 + 4u;
    RND(13) RND(15) RND(26) RND(6)  x0 += k2; x1 += k0 + 5u;
#undef RND
    y0 = x0; y1 = x1;
}

// randint(key(1),(L,U),0,L): k1,k2 = split(key); idx = lower_bits(k2) & 4095
// partitionable split: k2 = threefry((0,1),(0,1)); bits: ctr (0,j), y0^y1.
__global__ void k_idx() {
    int j = blockIdx.x * blockDim.x + threadIdx.x;
    if (j >= L_ * U_) return;
    uint32_t k2a, k2b;
    threefry2x32(0u, 1u, 0u, 1u, k2a, k2b);
    uint32_t z0, z1;
    threefry2x32(k2a, k2b, 0u, (uint32_t)j, z0, z1);
    g_idx[j] = (int)((z0 ^ z1) & (uint32_t)(L_ - 1));
}

// ---------------- M = max_s(QK_s) - sum_s(QK_s)/L ----------------
// one warp per (bh,q); two samples/iter (one per half-warp), float4 rows
__global__ void k_M(const float* __restrict__ Q, const float* __restrict__ K) {
    int w = (blockIdx.x * blockDim.x + threadIdx.x) >> 5;
    int lane = threadIdx.x & 31;
    if (w >= BH_ * L_) return;
    int q  = w & (L_ - 1);
    int bh = w >> 12;
    int b = bh >> 3, h = bh & 7;
    int half = lane >> 4;
    int lpos = lane & 15;

    const float4* qrow = (const float4*)(Q + ((b * L_ + q) * H_ + h) * D_);
    float4 qv = __ldg(qrow + lpos);

    const int* idxp = g_idx + q * U_;
    int i0 = __ldg(idxp + lane);
    int i1 = (lane + 32 < U_) ? __ldg(idxp + lane + 32) : 0;

    const float* Kb = K + (b * L_ * H_ + h) * D_;

#define FETCH_ROW(sv, rv) {                                   \
        int sc_ = (sv) & 31;                                  \
        int a_  = __shfl_sync(0xffffffffu, i0, sc_);          \
        int c_  = __shfl_sync(0xffffffffu, i1, sc_);          \
        rv = ((sv) < 32) ? a_ : c_; }

    int s0 = half;
    int r0; FETCH_ROW(s0, r0);
    float4 kv = __ldg(((const float4*)(Kb + r0 * (H_ * D_))) + lpos);

    float mx = -INFINITY, sm = 0.f;
#pragma unroll 1
    for (int t = 0; t < 23; t++) {
        int s = 2 * t + half;
        float4 kvn = make_float4(0.f, 0.f, 0.f, 0.f);
        if (t < 22) {
            int sn = 2 * (t + 1) + half;
            if (sn > 44) sn = 44;
            int rn; FETCH_ROW(sn, rn);
            kvn = __ldg(((const float4*)(Kb + rn * (H_ * D_))) + lpos);
        }
        float p = qv.x * kv.x + qv.y * kv.y + qv.z * kv.z + qv.w * kv.w;
        p += __shfl_xor_sync(0xffffffffu, p, 8);
        p += __shfl_xor_sync(0xffffffffu, p, 4);
        p += __shfl_xor_sync(0xffffffffu, p, 2);
        p += __shfl_xor_sync(0xffffffffu, p, 1);
        if (s < U_) { mx = fmaxf(mx, p); sm += p; }
        kv = kvn;
    }
#undef FETCH_ROW
    float omx = __shfl_xor_sync(0xffffffffu, mx, 16);
    float osm = __shfl_xor_sync(0xffffffffu, sm, 16);
    mx = fmaxf(mx, omx);
    sm += osm;
    if (lane == 0) g_M[bh * L_ + q] = mx - sm * (1.0f / (float)L_);
}

// ---------------- top-45 selection (lowest-index tie-break, rank order) ---
__global__ void k_topk(const float* __restrict__ Q) {
    __shared__ float sM[L_];
    __shared__ float swv[16];
    __shared__ int   swi[16];
    __shared__ int   ssel[U_];
    int bh = blockIdx.x;
    int tid = threadIdx.x;          // 512 threads
    int b = bh >> 3, h = bh & 7;

    for (int i = tid; i < L_; i += 512) sM[i] = g_M[bh * L_ + i];
    __syncthreads();

    for (int it = 0; it < U_; it++) {
        float bv = -INFINITY;
        int bi = -1;
        for (int i = tid; i < L_; i += 512) {
            float v = sM[i];
            if (v > bv || (v == bv && (unsigned)i < (unsigned)bi)) { bv = v; bi = i; }
        }
#pragma unroll
        for (int o = 16; o; o >>= 1) {
            float ov = __shfl_xor_sync(0xffffffffu, bv, o);
            int   oi = __shfl_xor_sync(0xffffffffu, bi, o);
            if (ov > bv || (ov == bv && (unsigned)oi < (unsigned)bi)) { bv = ov; bi = oi; }
        }
        if ((tid & 31) == 0) { swv[tid >> 5] = bv; swi[tid >> 5] = bi; }
        __syncthreads();
        if (tid < 32) {
            float v2 = (tid < 16) ? swv[tid] : -INFINITY;
            int   i2 = (tid < 16) ? swi[tid] : -1;
#pragma unroll
            for (int o = 8; o; o >>= 1) {
                float ov = __shfl_xor_sync(0xffffffffu, v2, o);
                int   oi = __shfl_xor_sync(0xffffffffu, i2, o);
                if (ov > v2 || (ov == v2 && (unsigned)oi < (unsigned)i2)) { v2 = ov; i2 = oi; }
            }
            if (tid == 0) {
                ssel[it] = i2;
                sM[i2] = -INFINITY;
            }
        }
        __syncthreads();
    }
    for (int t = tid; t < U_ * D_; t += 512) {
        int r = t >> 6, d = t & 63;
        g_qsel[(bh * U_ + r) * D_ + d] = Q[((b * L_ + ssel[r]) * H_ + h) * D_ + d];
    }
}

// ---------------- fused scores + chunk softmax + P@V ----------------
// grid (NCH_, BH_), 256 threads. smem: Q tile + score tile (~35KB)
__global__ void k_flash(const float* __restrict__ K, const float* __restrict__ V,
                        const int* __restrict__ mask) {
    __shared__ float4 sQ[U_][D_ / 4];   // 11.5 KB
    __shared__ float  sS[U_][CH_];      // 23 KB
    __shared__ float  smx[U_], slx[U_];
    int ch = blockIdx.x, bh = blockIdx.y;
    int b = bh >> 3, h = bh & 7;
    int tid = threadIdx.x;
    int k0 = ch * CH_;

    for (int t = tid; t < U_ * (D_ / 4); t += 256)
        sQ[t >> 4][t & 15] = ((const float4*)g_qsel)[bh * U_ * (D_ / 4) + t];
    __syncthreads();

    // phase 1: scores for this key chunk (half-warp split over u)
    {
        int kk = tid & 127;
        int half = tid >> 7;
        const float4* krow = (const float4*)(K + (((size_t)b * L_ + k0 + kk) * H_ + h) * D_);
        float4 kr[16];
#pragma unroll
        for (int i = 0; i < 16; i++) kr[i] = __ldg(krow + i);
        int m = __ldg(mask + b * L_ + k0 + kk);
        int u0 = half ? 23 : 0, u1 = half ? U_ : 23;
        for (int u = u0; u < u1; u++) {
            float a0 = 0.f, a1 = 0.f, a2 = 0.f, a3 = 0.f;   // 4-way ILP
#pragma unroll
            for (int i = 0; i < 16; i++) {
                float4 qv = sQ[u][i];
                a0 += qv.x * kr[i].x;
                a1 += qv.y * kr[i].y;
                a2 += qv.z * kr[i].z;
                a3 += qv.w * kr[i].w;
            }
            float s = (a0 + a1) + (a2 + a3);
            sS[u][kk] = (m == 0) ? -1e30f : s * 0.125f;
        }
    }
    __syncthreads();

    // phase 1b: per-u chunk max/sumexp; write P back into sS
    {
        int w = tid >> 5, lane = tid & 31;
        for (int u = w; u < U_; u += 8) {
            float4 v = ((const float4*)sS[u])[lane];
            float mx = fmaxf(fmaxf(v.x, v.y), fmaxf(v.z, v.w));
#pragma unroll
            for (int o = 16; o; o >>= 1) mx = fmaxf(mx, __shfl_xor_sync(0xffffffffu, mx, o));
            v.x = expf(v.x - mx); v.y = expf(v.y - mx);
            v.z = expf(v.z - mx); v.w = expf(v.w - mx);
            float s = (v.x + v.y) + (v.z + v.w);
#pragma unroll
            for (int o = 16; o; o >>= 1) s += __shfl_xor_sync(0xffffffffu, s, o);
            ((float4*)sS[u])[lane] = v;
            if (lane == 0) { smx[u] = mx; slx[u] = s; }
        }
    }
    __syncthreads();

    // phase 2: P @ V. thread: ug = tid>>5 (8 groups of u), d2 = tid&31 (float2 of d)
    {
        int ug = tid >> 5, d2 = tid & 31;
        float2 acc[6];
#pragma unroll
        for (int i = 0; i < 6; i++) acc[i] = make_float2(0.f, 0.f);
        const float2* Vb = (const float2*)(V + (((size_t)b * L_ + k0) * H_ + h) * D_) + d2;
        const int vstride = H_ * D_ / 2;   // 256 float2

        for (int k4 = 0; k4 < CH_; k4 += 4) {
            float2 v0 = __ldg(Vb + (size_t)(k4 + 0) * vstride);
            float2 v1 = __ldg(Vb + (size_t)(k4 + 1) * vstride);
            float2 v2 = __ldg(Vb + (size_t)(k4 + 2) * vstride);
            float2 v3 = __ldg(Vb + (size_t)(k4 + 3) * vstride);
#pragma unroll
            for (int i = 0; i < 6; i++) {
                int u = ug + 8 * i;
                if (u < U_) {
                    float4 p = ((const float4*)sS[u])[k4 >> 2];
                    acc[i].x += p.x * v0.x + p.y * v1.x + p.z * v2.x + p.w * v3.x;
                    acc[i].y += p.x * v0.y + p.y * v1.y + p.z * v2.y + p.w * v3.y;
                }
            }
        }
#pragma unroll
        for (int i = 0; i < 6; i++) {
            int u = ug + 8 * i;
            if (u < U_) {
                float* dst = g_pacc + ((((size_t)ch * BH_ + bh) * U_ + u) * D_) + 2 * d2;
                dst[0] = acc[i].x; dst[1] = acc[i].y;
            }
        }
        if (tid < U_) {
            g_pm[((size_t)ch * BH_ + bh) * U_ + tid] = smx[tid];
            g_pl[((size_t)ch * BH_ + bh) * U_ + tid] = slx[tid];
        }
    }
}

// ---------------- merge chunk partials, write (b, rank, h, d) -------------
__global__ void k_merge(float* __restrict__ out) {
    int u = blockIdx.x, bh = blockIdx.y;
    int b = bh >> 3, h = bh & 7;
    int d = threadIdx.x;

    float M = -1e30f;
#pragma unroll 1
    for (int ch = 0; ch < NCH_; ch++)
        M = fmaxf(M, g_pm[((size_t)ch * BH_ + bh) * U_ + u]);

    float Lsum = 0.f, o = 0.f;
#pragma unroll 1
    for (int ch = 0; ch < NCH_; ch++) {
        size_t base = (size_t)ch * BH_ + bh;
        float w = expf(g_pm[base * U_ + u] - M);
        Lsum += g_pl[base * U_ + u] * w;
        o += g_pacc[(base * U_ + u) * D_ + d] * w;
    }
    out[((b * U_ + u) * H_ + h) * D_ + d] = o / Lsum;
}

// ---------------- launch ----------------
extern "C" void kernel_launch(void* const* d_in, const int* in_sizes, int n_in,
                              void* d_out, int out_size) {
    const float* Q    = (const float*)d_in[0];
    const float* K    = (const float*)d_in[1];
    const float* V    = (const float*)d_in[2];
    const int*   mask = (const int*)d_in[3];
    float* out = (float*)d_out;

    k_idx<<<(L_ * U_ + 255) / 256, 256>>>();
    k_M<<<(BH_ * L_ * 32) / 256, 256>>>(Q, K);
    k_topk<<<BH_, 512>>>(Q);
    k_flash<<<dim3(NCH_, BH_), 256>>>(K, V, mask);
    k_merge<<<dim3(U_, BH_), 64>>>(out);
}